// round 4
// baseline (speedup 1.0000x reference)
#include <cuda_runtime.h>
#include <cstdint>

// Problem constants
#define BB 256      // batch
#define TT 512      // timesteps
#define DD 128      // input dim
#define HH 512      // hidden
#define KKTOT 640   // D + H (fused K per step)
#define CC 10       // classes

// Tiling
#define M_BLK 64            // batch rows per CTA
#define NH_BLK 16           // h-columns per CTA
#define NG_BLK 64           // gate columns per CTA (4 * NH_BLK)
#define KC 32               // k-chunk (20 chunks per step)
#define NT_N (HH / NH_BLK)  // 32 N-tiles
#define NT_M (BB / M_BLK)   // 4 M-tiles
#define GRID_SZ (NT_M * NT_N)  // 128 CTAs (all co-resident)
#define NTHR 256            // 8 warps -> 2 per SMSP (latency hiding)

#define WS_PAD 68                      // padded row stride (floats), 16B-aligned rows
#define WS_FLOATS (KKTOT * WS_PAD)     // 43520 floats = 174,080 B
#define ZBUF_FLOATS (KC * WS_PAD)      // 2176 floats per buffer

// Persistent device state (allocation-free scratch)
__device__ float g_h[2][BB * HH];               // h ping-pong, 1 MB
__device__ float g_partial[NT_N][BB][CC];       // partial logits per N-tile
__device__ unsigned g_bar_count;
__device__ unsigned g_bar_gen;

// ---------------- grid-wide barrier (sense via generation counter) ----------
__device__ __forceinline__ void grid_barrier() {
    __threadfence();          // publish h stores
    __syncthreads();
    if (threadIdx.x == 0) {
        unsigned old = *((volatile unsigned*)&g_bar_gen);   // read BEFORE arriving
        unsigned a = atomicAdd(&g_bar_count, 1u);
        if (a == GRID_SZ - 1u) {
            atomicExch(&g_bar_count, 0u);
            __threadfence();
            atomicAdd(&g_bar_gen, 1u);
        } else {
            while (*((volatile unsigned*)&g_bar_gen) == old) { }
        }
    }
    __syncthreads();
}

// ---------------- packed fp32x2 FMA (B300: 2x 3-reg FFMA throughput) -------
__device__ __forceinline__ void fma2(unsigned long long& acc,
                                     unsigned long long a,
                                     unsigned long long b) {
    asm("fma.rn.f32x2 %0, %1, %2, %0;" : "+l"(acc) : "l"(a), "l"(b));
}
__device__ __forceinline__ unsigned long long pack2(float v) {
    unsigned long long r;
    unsigned u = __float_as_uint(v);
    asm("mov.b64 %0, {%1, %1};" : "=l"(r) : "r"(u));
    return r;
}

// ---------------- fast activations (MUFU tanh) -----------------------------
__device__ __forceinline__ float fast_tanh(float x) {
    float y;
    asm("tanh.approx.f32 %0, %1;" : "=f"(y) : "f"(x));
    return y;
}
__device__ __forceinline__ float fast_sigmoid(float x) {
    return 0.5f * fast_tanh(0.5f * x) + 0.5f;
}

// ---------------- Z tile staging -------------------------------------------
// Z row m = concat(X[b=m0+m, t, 0:128], h_prev[b, 0:512]); staged transposed
// into SMEM as Zs[k][m]. Mapping: m = tid&63 (warp-consecutive -> conflict-free
// STS), kb = (tid>>6)*8 covers the 32-wide k-chunk in 4 groups of 8.
__device__ __forceinline__ void load_z(const float* __restrict__ X,
                                       const float* __restrict__ hprev,
                                       int m0, int t, int kc, int tid,
                                       float4& v0, float4& v1) {
    int m  = tid & 63;
    int kb = (tid >> 6) * 8;
    int kg = kc + kb;              // 8-aligned; never straddles the D boundary
    if (kg < DD) {
        const float* s = X + ((size_t)(m0 + m) * TT + t) * DD + kg;
        v0 = __ldg((const float4*)s);
        v1 = __ldg((const float4*)(s + 4));
    } else {
        const float* s = hprev + (size_t)(m0 + m) * HH + (kg - DD);
        v0 = __ldcg((const float4*)s);     // L2-coherent read of peer-written h
        v1 = __ldcg((const float4*)(s + 4));
    }
}
__device__ __forceinline__ void sts_z(float* zs, int tid, float4 v0, float4 v1) {
    int m  = tid & 63;
    int kb = (tid >> 6) * 8;
    float* p = zs + kb * WS_PAD + m;
    p[0 * WS_PAD] = v0.x; p[1 * WS_PAD] = v0.y; p[2 * WS_PAD] = v0.z; p[3 * WS_PAD] = v0.w;
    p[4 * WS_PAD] = v1.x; p[5 * WS_PAD] = v1.y; p[6 * WS_PAD] = v1.z; p[7 * WS_PAD] = v1.w;
}

// ---------------- persistent LSTM kernel -----------------------------------
__global__ void __launch_bounds__(NTHR, 1)
lstm_persistent(const float* __restrict__ X,
                const float* __restrict__ W_ih,
                const float* __restrict__ W_hh,
                const float* __restrict__ b_ih,
                const float* __restrict__ b_hh,
                const float* __restrict__ W_lin)
{
    extern __shared__ float smem[];
    float* Ws  = smem;                          // [KKTOT][WS_PAD], persistent
    float* Zb  = smem + WS_FLOATS;              // 2 x [KC][WS_PAD]
    float* bsm = Zb + 2 * ZBUF_FLOATS;          // [NG_BLK]

    const int tid   = threadIdx.x;
    const int cta   = blockIdx.x;
    const int mtile = cta >> 5;                 // / NT_N
    const int ntile = cta & (NT_N - 1);
    const int m0    = mtile * M_BLK;
    const int c0    = ntile * NH_BLK;
    const int tx    = tid & 15;                 // h-column within tile
    const int ty    = tid >> 4;                 // 0..15 ; rows ty*4 .. ty*4+3

    // ---- one-time: load W slice into SMEM, column n = 4*j + g <-> gate row
    // r = g*H + c0 + j (gate order i,f,g,o matches reference split).
    for (int idx = tid; idx < NG_BLK * KKTOT; idx += NTHR) {
        int k = idx >> 6;
        int n = idx & 63;
        int j = n >> 2, g = n & 3;
        int r = g * HH + c0 + j;
        float v = (k < DD) ? W_ih[r * DD + k] : W_hh[r * HH + (k - DD)];
        Ws[k * WS_PAD + n] = v;
    }
    if (tid < NG_BLK) {
        int j = tid >> 2, g = tid & 3;
        int r = g * HH + c0 + j;
        bsm[tid] = b_ih[r] + b_hh[r];
    }
    // zero h ping buffer 0 (each CTA zeroes a 1024-float slice)
    {
        const int per = (BB * HH) / GRID_SZ;
        float* p = &g_h[0][(size_t)cta * per];
        for (int i = tid; i < per; i += NTHR) p[i] = 0.f;
    }
    __syncthreads();

    float bias_r[4];
#pragma unroll
    for (int g = 0; g < 4; g++) bias_r[g] = bsm[tx * 4 + g];

    grid_barrier();   // h0 zeros + everyone's W loaded

    unsigned long long acc2[2][4];
    float c_st[4], hsum[4];
#pragma unroll
    for (int i = 0; i < 4; i++) { c_st[i] = 0.f; hsum[i] = 0.f; }

    for (int t = 0; t < TT; t++) {
        const float* hprev = g_h[t & 1];
        float* hnext = g_h[(t + 1) & 1];
#pragma unroll
        for (int p = 0; p < 2; p++)
#pragma unroll
            for (int j = 0; j < 4; j++) acc2[p][j] = 0ull;

        // prefetch chunk 0
        float4 n0, n1;
        load_z(X, hprev, m0, t, 0, tid, n0, n1);
        sts_z(Zb, tid, n0, n1);
        __syncthreads();

#pragma unroll 1
        for (int kc = 0; kc < KKTOT; kc += KC) {
            const float* cur = Zb + ((kc / KC) & 1) * ZBUF_FLOATS;
            float* nxt       = Zb + (((kc / KC) + 1) & 1) * ZBUF_FLOATS;
            const bool more = (kc + KC) < KKTOT;
            if (more) load_z(X, hprev, m0, t, kc + KC, tid, n0, n1);

#pragma unroll
            for (int kk = 0; kk < KC; kk++) {
                const float4 wv = *reinterpret_cast<const float4*>(
                    Ws + (kc + kk) * WS_PAD + (tx << 2));
                unsigned long long w0 = pack2(wv.x), w1 = pack2(wv.y),
                                   w2 = pack2(wv.z), w3 = pack2(wv.w);
                const ulonglong2 za = *reinterpret_cast<const ulonglong2*>(
                    cur + kk * WS_PAD + (ty << 2));
                fma2(acc2[0][0], za.x, w0); fma2(acc2[0][1], za.x, w1);
                fma2(acc2[0][2], za.x, w2); fma2(acc2[0][3], za.x, w3);
                fma2(acc2[1][0], za.y, w0); fma2(acc2[1][1], za.y, w1);
                fma2(acc2[1][2], za.y, w2); fma2(acc2[1][3], za.y, w3);
            }
            if (more) sts_z(nxt, tid, n0, n1);
            __syncthreads();
        }

        // ---- epilogue: gates -> (c, h); c and sum(h) stay in registers ----
#pragma unroll
        for (int p = 0; p < 2; p++) {
            float ga[4][2];
#pragma unroll
            for (int j = 0; j < 4; j++) {
                unsigned lo, hi;
                asm("mov.b64 {%0, %1}, %2;" : "=r"(lo), "=r"(hi) : "l"(acc2[p][j]));
                ga[j][0] = __uint_as_float(lo) + bias_r[j];
                ga[j][1] = __uint_as_float(hi) + bias_r[j];
            }
#pragma unroll
            for (int hf = 0; hf < 2; hf++) {
                const int i = p * 2 + hf;
                float ig = fast_sigmoid(ga[0][hf]);
                float fg = fast_sigmoid(ga[1][hf]);
                float gg = fast_tanh(ga[2][hf]);
                float og = fast_sigmoid(ga[3][hf]);
                float cv = fg * c_st[i] + ig * gg;
                c_st[i] = cv;
                float hv = og * fast_tanh(cv);
                hsum[i] += hv;
                hnext[(size_t)(m0 + ty * 4 + i) * HH + c0 + tx] = hv;
            }
        }
        grid_barrier();
    }

    // ---- logits partials: reduce over this CTA's 16 h-columns (shuffle) ----
    // tx lives in lane bits [0:4); xor-reduce over 8/4/2/1 stays within the
    // 16-lane half holding one ty value.
    const float inv_t = 1.f / (float)TT;
#pragma unroll
    for (int i = 0; i < 4; i++) {
        const int b = m0 + ty * 4 + i;
        const float hm = hsum[i] * inv_t;
#pragma unroll
        for (int cls = 0; cls < CC; cls++) {
            float v = hm * __ldg(&W_lin[cls * HH + c0 + tx]);
            v += __shfl_xor_sync(0xffffffffu, v, 8);
            v += __shfl_xor_sync(0xffffffffu, v, 4);
            v += __shfl_xor_sync(0xffffffffu, v, 2);
            v += __shfl_xor_sync(0xffffffffu, v, 1);
            if (tx == 0) g_partial[ntile][b][cls] = v;
        }
    }
}

// ---------------- deterministic final reduction ----------------------------
__global__ void lstm_finalize(const float* __restrict__ b_lin,
                              float* __restrict__ out) {
    int idx = blockIdx.x * blockDim.x + threadIdx.x;
    if (idx < BB * CC) {
        int b = idx / CC, cls = idx % CC;
        float s = b_lin[cls];
#pragma unroll
        for (int n = 0; n < NT_N; n++) s += g_partial[n][b][cls];
        out[idx] = s;
    }
}

extern "C" void kernel_launch(void* const* d_in, const int* in_sizes, int n_in,
                              void* d_out, int out_size) {
    const float* X     = (const float*)d_in[0];
    const float* W_ih  = (const float*)d_in[1];
    const float* W_hh  = (const float*)d_in[2];
    const float* b_ih  = (const float*)d_in[3];
    const float* b_hh  = (const float*)d_in[4];
    const float* W_lin = (const float*)d_in[5];
    const float* b_lin = (const float*)d_in[6];

    const int smem_bytes = (WS_FLOATS + 2 * ZBUF_FLOATS + NG_BLK) * (int)sizeof(float);
    cudaFuncSetAttribute(lstm_persistent,
                         cudaFuncAttributeMaxDynamicSharedMemorySize, smem_bytes);

    lstm_persistent<<<GRID_SZ, NTHR, smem_bytes>>>(X, W_ih, W_hh, b_ih, b_hh, W_lin);
    lstm_finalize<<<(BB * CC + 255) / 256, 256>>>(b_lin, (float*)d_out);
}

// round 5
// speedup vs baseline: 1.1979x; 1.1979x over previous
#include <cuda_runtime.h>
#include <cstdint>

// Problem constants
#define BB 256      // batch
#define TT 512      // timesteps
#define DD 128      // input dim
#define HH 512      // hidden
#define KKTOT 640   // D + H (fused K per step)
#define KHALF 320   // K per k-group
#define CC 10       // classes

// Tiling
#define M_BLK 64            // batch rows per CTA
#define NH_BLK 16           // h-columns per CTA
#define NG_BLK 64           // gate columns per CTA (4 * NH_BLK)
#define KC 32               // k-chunk (10 chunks per k-group per step)
#define NT_N (HH / NH_BLK)  // 32 N-tiles
#define NT_M (BB / M_BLK)   // 4 M-tiles
#define GRID_SZ (NT_M * NT_N)  // 128 CTAs (all co-resident)
#define NTHR 256            // 2 k-groups x 128 threads; 2 warps/SMSP

#define WS_PAD 68                      // padded row stride (floats)
#define WS_FLOATS (KKTOT * WS_PAD)     // 43520 floats = 174,080 B
#define ZBUF_FLOATS (KC * WS_PAD)      // 2176 floats per buffer (8704 B)
// 4 Z buffers total: 2 per k-group (double buffer)

// Persistent device state (allocation-free scratch)
__device__ float g_h[2][BB * HH];               // h ping-pong, 1 MB
__device__ float g_partial[NT_N][BB][CC];       // partial logits per N-tile
__device__ unsigned g_bar_count;
__device__ unsigned g_bar_gen;

// ---------------- grid-wide barrier (sense via generation counter) ----------
__device__ __forceinline__ void grid_barrier() {
    __threadfence();          // publish h stores
    __syncthreads();
    if (threadIdx.x == 0) {
        unsigned old = *((volatile unsigned*)&g_bar_gen);   // read BEFORE arriving
        unsigned a = atomicAdd(&g_bar_count, 1u);
        if (a == GRID_SZ - 1u) {
            atomicExch(&g_bar_count, 0u);
            __threadfence();
            atomicAdd(&g_bar_gen, 1u);
        } else {
            while (*((volatile unsigned*)&g_bar_gen) == old) { }
        }
    }
    __syncthreads();
}

// ---------------- packed fp32x2 ops ----------------------------------------
__device__ __forceinline__ void fma2(unsigned long long& acc,
                                     unsigned long long a,
                                     unsigned long long b) {
    asm("fma.rn.f32x2 %0, %1, %2, %0;" : "+l"(acc) : "l"(a), "l"(b));
}
__device__ __forceinline__ unsigned long long add2(unsigned long long a,
                                                   unsigned long long b) {
    unsigned long long r;
    asm("add.rn.f32x2 %0, %1, %2;" : "=l"(r) : "l"(a), "l"(b));
    return r;
}
__device__ __forceinline__ unsigned long long pack2(float v) {
    unsigned long long r;
    unsigned u = __float_as_uint(v);
    asm("mov.b64 %0, {%1, %1};" : "=l"(r) : "r"(u));
    return r;
}

// ---------------- fast activations (MUFU tanh) -----------------------------
__device__ __forceinline__ float fast_tanh(float x) {
    float y;
    asm("tanh.approx.f32 %0, %1;" : "=f"(y) : "f"(x));
    return y;
}
__device__ __forceinline__ float fast_sigmoid(float x) {
    return 0.5f * fast_tanh(0.5f * x) + 0.5f;
}

// ---------------- Z tile staging (per k-group: 128 thr x 16 floats) --------
// Z row m = concat(X[b, t, :], h_prev[b, :]); staged transposed as Zs[k][m].
// Thread covers 16 consecutive k at column m = lidx&63, kb = (lidx>>6)*16.
// kg0 is 16-aligned, so a thread's 16 k-rows never straddle the X/h boundary.
__device__ __forceinline__ void load_z16(const float* __restrict__ X,
                                         const float* __restrict__ hprev,
                                         int m0, int t, int kg0, int m,
                                         float4 v[4]) {
    if (kg0 < DD) {
        const float* s = X + ((size_t)(m0 + m) * TT + t) * DD + kg0;
        v[0] = __ldg((const float4*)s);
        v[1] = __ldg((const float4*)(s + 4));
        v[2] = __ldg((const float4*)(s + 8));
        v[3] = __ldg((const float4*)(s + 12));
    } else {
        const float* s = hprev + (size_t)(m0 + m) * HH + (kg0 - DD);
        v[0] = __ldcg((const float4*)s);
        v[1] = __ldcg((const float4*)(s + 4));
        v[2] = __ldcg((const float4*)(s + 8));
        v[3] = __ldcg((const float4*)(s + 12));
    }
}
__device__ __forceinline__ void sts_z16(float* zs, int kb, int m,
                                        const float4 v[4]) {
    float* p = zs + kb * WS_PAD + m;   // rows kb..kb+15, column m (lanes consecutive)
#pragma unroll
    for (int j = 0; j < 4; j++) {
        p[(j * 4 + 0) * WS_PAD] = v[j].x;
        p[(j * 4 + 1) * WS_PAD] = v[j].y;
        p[(j * 4 + 2) * WS_PAD] = v[j].z;
        p[(j * 4 + 3) * WS_PAD] = v[j].w;
    }
}

// ---------------- persistent LSTM kernel -----------------------------------
__global__ void __launch_bounds__(NTHR, 1)
lstm_persistent(const float* __restrict__ X,
                const float* __restrict__ W_ih,
                const float* __restrict__ W_hh,
                const float* __restrict__ b_ih,
                const float* __restrict__ b_hh,
                const float* __restrict__ W_lin)
{
    extern __shared__ float smem[];
    float* Ws  = smem;                          // [KKTOT][WS_PAD], persistent
    float* Zb  = smem + WS_FLOATS;              // 4 x [KC][WS_PAD] (2 per group)
    float* bsm = Zb + 4 * ZBUF_FLOATS;          // [NG_BLK]

    const int tid   = threadIdx.x;
    const int cta   = blockIdx.x;
    const int mtile = cta >> 5;                 // / NT_N
    const int ntile = cta & (NT_N - 1);
    const int m0    = mtile * M_BLK;
    const int c0    = ntile * NH_BLK;

    const int grp   = tid >> 7;                 // k-group: 0 or 1
    const int lidx  = tid & 127;
    const int tx    = lidx & 15;                // h-column within tile
    const int ty    = lidx >> 4;                // 0..7 ; rows ty*8 .. ty*8+7
    const int kbase = grp * KHALF;

    // staging coords
    const int sm = lidx & 63;                   // column m
    const int skb = (lidx >> 6) * 16;           // k offset within chunk (0 or 16)
    float* Zg = Zb + grp * (2 * ZBUF_FLOATS);

    // ---- one-time: load W slice into SMEM, column n = 4*j + g <-> gate row
    // r = g*H + c0 + j (gate order i,f,g,o matches reference split).
    for (int idx = tid; idx < NG_BLK * KKTOT; idx += NTHR) {
        int k = idx >> 6;
        int n = idx & 63;
        int j = n >> 2, g = n & 3;
        int r = g * HH + c0 + j;
        float v = (k < DD) ? W_ih[r * DD + k] : W_hh[r * HH + (k - DD)];
        Ws[k * WS_PAD + n] = v;
    }
    if (tid < NG_BLK) {
        int j = tid >> 2, g = tid & 3;
        int r = g * HH + c0 + j;
        bsm[tid] = b_ih[r] + b_hh[r];
    }
    // zero h ping buffer 0 (each CTA zeroes a slice)
    {
        const int per = (BB * HH) / GRID_SZ;
        float* p = &g_h[0][(size_t)cta * per];
        for (int i = tid; i < per; i += NTHR) p[i] = 0.f;
    }
    __syncthreads();

    float bias_r[4];
#pragma unroll
    for (int g = 0; g < 4; g++) bias_r[g] = bsm[tx * 4 + g];

    grid_barrier();   // h0 zeros + everyone's W loaded

    unsigned long long acc2[4][4];              // [row-pair][gate]
    float c_st[8], hsum[8];                     // live in group 0 only
#pragma unroll
    for (int i = 0; i < 8; i++) { c_st[i] = 0.f; hsum[i] = 0.f; }

    unsigned long long* red = (unsigned long long*)Zb;   // reduction scratch (16KB)

    for (int t = 0; t < TT; t++) {
        const float* hprev = g_h[t & 1];
        float* hnext = g_h[(t + 1) & 1];
#pragma unroll
        for (int p = 0; p < 4; p++)
#pragma unroll
            for (int j = 0; j < 4; j++) acc2[p][j] = 0ull;

        // prefetch chunk 0 of this group
        float4 v[4];
        load_z16(X, hprev, m0, t, kbase + skb, sm, v);
        sts_z16(Zg, skb, sm, v);
        __syncthreads();

#pragma unroll 1
        for (int kc = 0; kc < KHALF; kc += KC) {
            const float* cur = Zg + ((kc / KC) & 1) * ZBUF_FLOATS;
            float* nxt       = Zg + (((kc / KC) + 1) & 1) * ZBUF_FLOATS;
            const bool more = (kc + KC) < KHALF;
            if (more) load_z16(X, hprev, m0, t, kbase + kc + KC + skb, sm, v);

            const float* wrow = Ws + (kbase + kc) * WS_PAD + (tx << 2);
#pragma unroll
            for (int kk = 0; kk < KC; kk++) {
                const float4 wv = *reinterpret_cast<const float4*>(wrow + kk * WS_PAD);
                unsigned long long w0 = pack2(wv.x), w1 = pack2(wv.y),
                                   w2 = pack2(wv.z), w3 = pack2(wv.w);
                const float* zr = cur + kk * WS_PAD + (ty << 3);
                const ulonglong2 za = *reinterpret_cast<const ulonglong2*>(zr);
                const ulonglong2 zc = *reinterpret_cast<const ulonglong2*>(zr + 4);
                fma2(acc2[0][0], za.x, w0); fma2(acc2[0][1], za.x, w1);
                fma2(acc2[0][2], za.x, w2); fma2(acc2[0][3], za.x, w3);
                fma2(acc2[1][0], za.y, w0); fma2(acc2[1][1], za.y, w1);
                fma2(acc2[1][2], za.y, w2); fma2(acc2[1][3], za.y, w3);
                fma2(acc2[2][0], zc.x, w0); fma2(acc2[2][1], zc.x, w1);
                fma2(acc2[2][2], zc.x, w2); fma2(acc2[2][3], zc.x, w3);
                fma2(acc2[3][0], zc.y, w0); fma2(acc2[3][1], zc.y, w1);
                fma2(acc2[3][2], zc.y, w2); fma2(acc2[3][3], zc.y, w3);
            }
            if (more) sts_z16(nxt, skb, sm, v);
            __syncthreads();
        }

        // ---- k-split reduction: group 1 -> SMEM, group 0 adds --------------
        if (grp == 1) {
#pragma unroll
            for (int p = 0; p < 4; p++)
#pragma unroll
                for (int j = 0; j < 4; j++)
                    red[(p * 4 + j) * 128 + lidx] = acc2[p][j];
        }
        __syncthreads();

        if (grp == 0) {
#pragma unroll
            for (int p = 0; p < 4; p++) {
                float ga[4][2];
#pragma unroll
                for (int j = 0; j < 4; j++) {
                    unsigned long long s =
                        add2(acc2[p][j], red[(p * 4 + j) * 128 + lidx]);
                    unsigned lo, hi;
                    asm("mov.b64 {%0, %1}, %2;" : "=r"(lo), "=r"(hi) : "l"(s));
                    ga[j][0] = __uint_as_float(lo) + bias_r[j];
                    ga[j][1] = __uint_as_float(hi) + bias_r[j];
                }
#pragma unroll
                for (int hf = 0; hf < 2; hf++) {
                    const int i = p * 2 + hf;
                    float ig = fast_sigmoid(ga[0][hf]);
                    float fg = fast_sigmoid(ga[1][hf]);
                    float gg = fast_tanh(ga[2][hf]);
                    float og = fast_sigmoid(ga[3][hf]);
                    float cv = fg * c_st[i] + ig * gg;
                    c_st[i] = cv;
                    float hv = og * fast_tanh(cv);
                    hsum[i] += hv;
                    // rows: acc pair p holds m = ty*8 + {2p, 2p+1}
                    hnext[(size_t)(m0 + ty * 8 + 2 * p + hf) * HH + c0 + tx] = hv;
                }
            }
        }
        grid_barrier();
    }

    // ---- logits partials (group 0 holds hsum): shuffle-reduce over tx ------
    const float inv_t = 1.f / (float)TT;
    if (grp == 0) {
#pragma unroll
        for (int i = 0; i < 8; i++) {
            // acc pair layout: m = ty*8 + i, where i = 2p+hf and hsum index i matches
            const int b = m0 + ty * 8 + i;
            const float hm = hsum[i] * inv_t;
#pragma unroll
            for (int cls = 0; cls < CC; cls++) {
                float v2 = hm * __ldg(&W_lin[cls * HH + c0 + tx]);
                v2 += __shfl_xor_sync(0xffffffffu, v2, 8);
                v2 += __shfl_xor_sync(0xffffffffu, v2, 4);
                v2 += __shfl_xor_sync(0xffffffffu, v2, 2);
                v2 += __shfl_xor_sync(0xffffffffu, v2, 1);
                if (tx == 0) g_partial[ntile][b][cls] = v2;
            }
        }
    }
}

// ---------------- deterministic final reduction ----------------------------
__global__ void lstm_finalize(const float* __restrict__ b_lin,
                              float* __restrict__ out) {
    int idx = blockIdx.x * blockDim.x + threadIdx.x;
    if (idx < BB * CC) {
        int b = idx / CC, cls = idx % CC;
        float s = b_lin[cls];
#pragma unroll
        for (int n = 0; n < NT_N; n++) s += g_partial[n][b][cls];
        out[idx] = s;
    }
}

// no-op padding so ncu's "-s 5" lands on lstm_persistent (5 launches/call:
// correctness run = indices 0..4, first replay launch = index 5 = persistent)
__global__ void lstm_nop() {}

extern "C" void kernel_launch(void* const* d_in, const int* in_sizes, int n_in,
                              void* d_out, int out_size) {
    const float* X     = (const float*)d_in[0];
    const float* W_ih  = (const float*)d_in[1];
    const float* W_hh  = (const float*)d_in[2];
    const float* b_ih  = (const float*)d_in[3];
    const float* b_hh  = (const float*)d_in[4];
    const float* W_lin = (const float*)d_in[5];
    const float* b_lin = (const float*)d_in[6];

    const int smem_bytes = (WS_FLOATS + 4 * ZBUF_FLOATS + NG_BLK) * (int)sizeof(float);
    cudaFuncSetAttribute(lstm_persistent,
                         cudaFuncAttributeMaxDynamicSharedMemorySize, smem_bytes);

    lstm_persistent<<<GRID_SZ, NTHR, smem_bytes>>>(X, W_ih, W_hh, b_ih, b_hh, W_lin);
    lstm_finalize<<<(BB * CC + 255) / 256, 256>>>(b_lin, (float*)d_out);
    lstm_nop<<<1, 32>>>();
    lstm_nop<<<1, 32>>>();
    lstm_nop<<<1, 32>>>();
}